// round 3
// baseline (speedup 1.0000x reference)
#include <cuda_runtime.h>

#define NQ       12
#define DIM      4096
#define THREADS  256
#define NCLASSES 10
#define NFEAT    36

typedef unsigned long long u64;

struct Cx { float x, y; };
__device__ __forceinline__ Cx cmul(Cx a, Cx b) {
    return Cx{a.x * b.x - a.y * b.y, a.x * b.y + a.y * b.x};
}

// ---- f32x2 packed helpers (FFMA2 path, sm_103a) ----
__device__ __forceinline__ u64 pk(float lo, float hi) {
    u64 r; asm("mov.b64 %0, {%1,%2};" : "=l"(r) : "f"(lo), "f"(hi)); return r;
}
__device__ __forceinline__ void upk(u64 v, float& lo, float& hi) {
    asm("mov.b64 {%0,%1}, %2;" : "=f"(lo), "=f"(hi) : "l"(v));
}
__device__ __forceinline__ u64 f2fma(u64 a, u64 b, u64 c) {
    u64 r; asm("fma.rn.f32x2 %0, %1, %2, %3;" : "=l"(r) : "l"(a), "l"(b), "l"(c)); return r;
}
__device__ __forceinline__ u64 f2mul(u64 a, u64 b) {
    u64 r; asm("mul.rn.f32x2 %0, %1, %2;" : "=l"(r) : "l"(a), "l"(b)); return r;
}
__device__ __forceinline__ u64 f2add(u64 a, u64 b) {
    u64 r; asm("add.rn.f32x2 %0, %1, %2;" : "=l"(r) : "l"(a), "l"(b)); return r;
}
__device__ __forceinline__ u64 splat(float x) { return pk(x, x); }
__device__ __forceinline__ u64 swap2(u64 v) { float lo, hi; upk(v, lo, hi); return pk(hi, lo); }

// ---- addressing (same swizzle as R2) ----
__device__ __forceinline__ int swzc(int i) { return i ^ ((i >> 5) & 31); }

template<int S0,int S1,int S2,int S3>
__device__ __forceinline__ int offj(int j) {
    return ((j & 1) << S0) | (((j >> 1) & 1) << S1) | (((j >> 2) & 1) << S2) | (((j >> 3) & 1) << S3);
}
template<int L0,int L1,int L2,int L3,int L4,int W0,int W1,int W2>
__device__ __forceinline__ int mkbase(int t) {
    return ((t & 1) << L0) | (((t >> 1) & 1) << L1) | (((t >> 2) & 1) << L2) |
           (((t >> 3) & 1) << L3) | (((t >> 4) & 1) << L4) |
           (((t >> 5) & 1) << W0) | (((t >> 6) & 1) << W1) | (((t >> 7) & 1) << W2);
}

// Load/store packed state: vector m holds amps j=2m (lo), j=2m+1 (hi)
template<int S0,int S1,int S2,int S3>
__device__ __forceinline__ void vld(u64 R[8], u64 I[8], const float* re, const float* im, int pb) {
#pragma unroll
    for (int m = 0; m < 8; m++) {
        const int ad0 = pb ^ swzc(offj<S0,S1,S2,S3>(2*m));
        const int ad1 = pb ^ swzc(offj<S0,S1,S2,S3>(2*m + 1));
        R[m] = pk(re[ad0], re[ad1]);
        I[m] = pk(im[ad0], im[ad1]);
    }
}
template<int S0,int S1,int S2,int S3>
__device__ __forceinline__ void vst(const u64 R[8], const u64 I[8], float* re, float* im, int pb) {
#pragma unroll
    for (int m = 0; m < 8; m++) {
        const int ad0 = pb ^ swzc(offj<S0,S1,S2,S3>(2*m));
        const int ad1 = pb ^ swzc(offj<S0,S1,S2,S3>(2*m + 1));
        float lo, hi;
        upk(R[m], lo, hi); re[ad0] = lo; re[ad1] = hi;
        upk(I[m], lo, hi); im[ad0] = lo; im[ad1] = hi;
    }
}

// ---- gate kernels ----
// GS layout: [0]u00x [1]u01x [2]u10x [3]u11x [4]u00y [5]u01y [6]u10y [7]u11y
//            [8]-u00y [9]-u01y [10]-u10y [11]-u11y   (all lane-splatted)
template<int K>  // 1q gate, local bit K>=1
__device__ __forceinline__ void v1q(u64 R[8], u64 I[8], const u64* g) {
    const u64 g0=g[0],g1=g[1],g2=g[2],g3=g[3],g4=g[4],g5=g[5],g6=g[6],g7=g[7];
    const u64 g8=g[8],g9=g[9],g10=g[10],g11=g[11];
#pragma unroll
    for (int m = 0; m < 8; m++) {
        if (!((m >> (K-1)) & 1)) {
            const int m1 = m | (1 << (K-1));
            const u64 a = R[m], ai = I[m], b = R[m1], bi = I[m1];
            R[m]  = f2fma(g0, a, f2fma(g8,  ai, f2fma(g1, b, f2mul(g9,  bi))));
            I[m]  = f2fma(g4, a, f2fma(g0,  ai, f2fma(g5, b, f2mul(g1,  bi))));
            R[m1] = f2fma(g2, a, f2fma(g10, ai, f2fma(g3, b, f2mul(g11, bi))));
            I[m1] = f2fma(g6, a, f2fma(g2,  ai, f2fma(g7, b, f2mul(g3,  bi))));
        }
    }
}

// GP layout: [0]A={u00x,u10x} [1]B={u01x,u11x} [2]C={u00y,u10y} [3]D={u01y,u11y} [4]Cn=-C [5]Dn=-D
__device__ __forceinline__ void v2q(u64 R[8], u64 I[8], const u64* p) {
    const u64 A=p[0],B=p[1],C=p[2],D=p[3],Cn=p[4],Dn=p[5];
#pragma unroll
    for (int m = 0; m < 8; m++) {
        float ar0, ar1, ai0, ai1;
        upk(R[m], ar0, ar1); upk(I[m], ai0, ai1);
        const u64 sr0 = splat(ar0), sr1 = splat(ar1), si0 = splat(ai0), si1 = splat(ai1);
        R[m] = f2fma(A, sr0, f2fma(Cn, si0, f2fma(B, sr1, f2mul(Dn, si1))));
        I[m] = f2fma(C, sr0, f2fma(A,  si0, f2fma(D, sr1, f2mul(B,  si1))));
    }
}
// first-gate special: imag state = 0
__device__ __forceinline__ void v2q_real(u64 R[8], u64 I[8], const u64* p) {
    const u64 A=p[0],B=p[1],C=p[2],D=p[3];
#pragma unroll
    for (int m = 0; m < 8; m++) {
        float ar0, ar1, d0, d1;
        upk(R[m], ar0, ar1); (void)d0; (void)d1;
        const u64 sr0 = splat(ar0), sr1 = splat(ar1);
        R[m] = f2fma(A, sr0, f2mul(B, sr1));
        I[m] = f2fma(C, sr0, f2mul(D, sr1));
    }
}

// CRX, ctrl bit KC>=1, tgt bit KT>=1.  cc:{c,c} ss:{s,s} ns:{-s,-s}
template<int KC,int KT>
__device__ __forceinline__ void vcrx(u64 R[8], u64 I[8], u64 cc2, u64 ss2, u64 ns2) {
#pragma unroll
    for (int m = 0; m < 8; m++) {
        if (((m >> (KC-1)) & 1) && !((m >> (KT-1)) & 1)) {
            const int m1 = m | (1 << (KT-1));
            const u64 a = R[m], ai = I[m], b = R[m1], bi = I[m1];
            R[m]  = f2fma(cc2, a,  f2mul(ss2, bi));
            I[m]  = f2fma(cc2, ai, f2mul(ns2, b));
            R[m1] = f2fma(cc2, b,  f2mul(ss2, ai));
            I[m1] = f2fma(cc2, bi, f2mul(ns2, a));
        }
    }
}
// CRX, tgt = lane bit (KT=0), ctrl KC>=1
template<int KC>
__device__ __forceinline__ void vcrx0t(u64 R[8], u64 I[8], u64 cc2, u64 ss2, u64 ns2) {
#pragma unroll
    for (int m = 0; m < 8; m++) {
        if ((m >> (KC-1)) & 1) {
            const u64 swI = swap2(I[m]), swR = swap2(R[m]);
            R[m] = f2fma(cc2, R[m], f2mul(ss2, swI));
            I[m] = f2fma(cc2, I[m], f2mul(ns2, swR));
        }
    }
}
// CRX, ctrl = lane bit (KC=0), tgt KT>=1.  g1:{1,c} gs:{0,s} gn:{0,-s}
template<int KT>
__device__ __forceinline__ void vcrx0c(u64 R[8], u64 I[8], u64 g1, u64 gs, u64 gn) {
#pragma unroll
    for (int m = 0; m < 8; m++) {
        if (!((m >> (KT-1)) & 1)) {
            const int m1 = m | (1 << (KT-1));
            const u64 Ra = R[m], Ia = I[m], Rb = R[m1], Ib = I[m1];
            R[m]  = f2fma(g1, Ra, f2mul(gs, Ib));
            I[m]  = f2fma(g1, Ia, f2mul(gn, Rb));
            R[m1] = f2fma(g1, Rb, f2mul(gs, Ia));
            I[m1] = f2fma(g1, Ib, f2mul(gn, Ra));
        }
    }
}

__device__ __forceinline__ void red_add(float v, float* dst) {
#pragma unroll
    for (int o = 16; o > 0; o >>= 1) v += __shfl_xor_sync(0xffffffffu, v, o);
    if ((threadIdx.x & 31) == 0) atomicAdd(dst, v);
}

// <X>,<Y> across local bit K>=1
template<int K>
__device__ __forceinline__ void vcross(const u64 R[8], const u64 I[8], float* feats, int q) {
    u64 cr2 = 0ull, cip = 0ull, cin = 0ull;
#pragma unroll
    for (int m = 0; m < 8; m++) {
        if (!((m >> (K-1)) & 1)) {
            const int m1 = m | (1 << (K-1));
            cr2 = f2fma(R[m], R[m1], f2fma(I[m], I[m1], cr2));
            cip = f2fma(R[m], I[m1], cip);
            cin = f2fma(I[m], R[m1], cin);
        }
    }
    float a, b;  upk(cr2, a, b); const float cr = a + b;
    float p0, p1, n0, n1; upk(cip, p0, p1); upk(cin, n0, n1);
    const float ci = (p0 - n0) + (p1 - n1);
    red_add(2.f * cr, &feats[q]);
    red_add(2.f * ci, &feats[NQ + q]);
}
// <X>,<Y> across the lane bit
__device__ __forceinline__ void vcross0(const u64 R[8], const u64 I[8], float* feats, int q) {
    float cr = 0.f, ci = 0.f;
#pragma unroll
    for (int m = 0; m < 8; m++) {
        float r0, r1, i0, i1;
        upk(R[m], r0, r1); upk(I[m], i0, i1);
        cr = fmaf(r0, r1, fmaf(i0, i1, cr));
        ci = fmaf(r0, i1, ci) - i0 * r1;
    }
    red_add(2.f * cr, &feats[q]);
    red_add(2.f * ci, &feats[NQ + q]);
}

__global__ __launch_bounds__(THREADS)
void qsim_kernel(const float* __restrict__ sv,
                 const float* __restrict__ angles,
                 const float* __restrict__ Wm,
                 const float* __restrict__ bv,
                 float* __restrict__ out)
{
    __shared__ float re[DIM];
    __shared__ float im[DIM];
    __shared__ u64 GS[24][12];  // splatted 1q coefs
    __shared__ u64 GP[24][6];   // lane-packed 1q coefs
    __shared__ u64 CC[24][3];   // crx {c,c},{s,s},{-s,-s}
    __shared__ u64 CL[24][3];   // crx ctrl-lane {1,c},{0,s},{0,-s}
    __shared__ float feats[NFEAT];

    const int tid  = threadIdx.x;
    const int bidx = blockIdx.x;

    if (tid < 24) {
        const int layer = tid / NQ;
        const int wire  = tid % NQ;
        const int base  = layer * 48;
        const float tx = angles[base + wire];
        const float ty = angles[base + 12 + wire];
        const float tz = angles[base + 24 + wire];
        const float cxv = cosf(0.5f*tx), sxv = sinf(0.5f*tx);
        const float cyv = cosf(0.5f*ty), syv = sinf(0.5f*ty);
        const float czv = cosf(0.5f*tz), szv = sinf(0.5f*tz);
        Cx m00{cyv*cxv,  syv*sxv};
        Cx m01{-syv*cxv, -cyv*sxv};
        Cx m10{syv*cxv,  -cyv*sxv};
        Cx m11{cyv*cxv,  -syv*sxv};
        Cx ezm{czv, -szv}, ezp{czv, szv};
        Cx u00 = cmul(ezm, m00), u01 = cmul(ezm, m01);
        Cx u10 = cmul(ezp, m10), u11 = cmul(ezp, m11);
        GS[tid][0]  = splat(u00.x); GS[tid][1]  = splat(u01.x);
        GS[tid][2]  = splat(u10.x); GS[tid][3]  = splat(u11.x);
        GS[tid][4]  = splat(u00.y); GS[tid][5]  = splat(u01.y);
        GS[tid][6]  = splat(u10.y); GS[tid][7]  = splat(u11.y);
        GS[tid][8]  = splat(-u00.y); GS[tid][9]  = splat(-u01.y);
        GS[tid][10] = splat(-u10.y); GS[tid][11] = splat(-u11.y);
        GP[tid][0] = pk(u00.x, u10.x); GP[tid][1] = pk(u01.x, u11.x);
        GP[tid][2] = pk(u00.y, u10.y); GP[tid][3] = pk(u01.y, u11.y);
        GP[tid][4] = pk(-u00.y, -u10.y); GP[tid][5] = pk(-u01.y, -u11.y);
        const float tc = angles[base + 36 + wire];
        const float c = cosf(0.5f*tc), s = sinf(0.5f*tc);
        CC[tid][0] = pk(c, c); CC[tid][1] = pk(s, s); CC[tid][2] = pk(-s, -s);
        CL[tid][0] = pk(1.f, c); CL[tid][1] = pk(0.f, s); CL[tid][2] = pk(0.f, -s);
    }
    if (tid < NFEAT) feats[tid] = 0.0f;
    __syncthreads();

    u64 R[8], I[8];

    // ---- Pass 1: S={8,9,10,11}; L0 1q wires 0-3; CRX slots 0,1,2 ----
    {
        const float* in = sv + (size_t)bidx * DIM;
#pragma unroll
        for (int m = 0; m < 8; m++) {
            R[m] = pk(in[((2*m) << 8) | tid], in[((2*m+1) << 8) | tid]);
            I[m] = 0ull;
        }
        v2q_real(R, I, GP[3]);                 // bit8 = wire3 (state still real)
        v1q<1>(R, I, GS[2]);
        v1q<2>(R, I, GS[1]);
        v1q<3>(R, I, GS[0]);
        vcrx<3,2>(R, I, CC[0][0], CC[0][1], CC[0][2]);   // CRX(0,1): bits(11,10)
        vcrx<2,1>(R, I, CC[1][0], CC[1][1], CC[1][2]);   // CRX(1,2): bits(10,9)
        vcrx0t<1>(R, I, CC[2][0], CC[2][1], CC[2][2]);   // CRX(2,3): bits(9,8)
        vst<8,9,10,11>(R, I, re, im, swzc(tid));
    }
    __syncthreads();

    // ---- Pass 2: S={5,6,7,8}; L0 1q wires 6,5,4; CRX slots 3,4,5 ----
    {
        const int pb = swzc(mkbase<0,1,2,3,4, 9,10,11>(tid));
        vld<5,6,7,8>(R, I, re, im, pb);
        v2q(R, I, GP[6]);
        v1q<1>(R, I, GS[5]);
        v1q<2>(R, I, GS[4]);
        vcrx<3,2>(R, I, CC[3][0], CC[3][1], CC[3][2]);
        vcrx<2,1>(R, I, CC[4][0], CC[4][1], CC[4][2]);
        vcrx0t<1>(R, I, CC[5][0], CC[5][1], CC[5][2]);
        vst<5,6,7,8>(R, I, re, im, pb);
    }
    __syncthreads();

    // ---- Pass 3: S={2,3,4,5}; L0 1q wires 9,8,7; CRX slots 6,7,8 ----
    {
        const int pb = swzc(mkbase<0,1,7,8,9, 6,10,11>(tid));
        vld<2,3,4,5>(R, I, re, im, pb);
        v2q(R, I, GP[9]);
        v1q<1>(R, I, GS[8]);
        v1q<2>(R, I, GS[7]);
        vcrx<3,2>(R, I, CC[6][0], CC[6][1], CC[6][2]);
        vcrx<2,1>(R, I, CC[7][0], CC[7][1], CC[7][2]);
        vcrx0t<1>(R, I, CC[8][0], CC[8][1], CC[8][2]);
        vst<2,3,4,5>(R, I, re, im, pb);
    }
    __syncthreads();

    // ---- Pass 4 (mega): S={0,1,2,11}; L0 tail + layer boundary + L1 head ----
    {
        const int pb = swzc(mkbase<3,4,5,6,7, 8,9,10>(tid));
        vld<0,1,2,11>(R, I, re, im, pb);
        v2q(R, I, GP[11]);                                  // L0 wire11 (bit0)
        v1q<1>(R, I, GS[10]);                               // L0 wire10 (bit1)
        vcrx<2,1>(R, I, CC[9][0],  CC[9][1],  CC[9][2]);    // CRX(9,10)
        vcrx0t<1>(R, I, CC[10][0], CC[10][1], CC[10][2]);   // CRX(10,11)
        vcrx0c<3>(R, I, CL[11][0], CL[11][1], CL[11][2]);   // CRX(11,0): ctrl bit0, tgt bit11
        v2q(R, I, GP[23]);                                  // L1 wire11 (bit0)
        v1q<1>(R, I, GS[22]);                               // L1 wire10
        v1q<2>(R, I, GS[21]);                               // L1 wire9
        v1q<3>(R, I, GS[12]);                               // L1 wire0 (bit11)
        vcrx0c<3>(R, I, CL[12][0], CL[12][1], CL[12][2]);   // L1 CRX(11,0)
        vcrx0t<1>(R, I, CC[13][0], CC[13][1], CC[13][2]);   // L1 CRX(10,11)
        vcrx<2,1>(R, I, CC[14][0], CC[14][1], CC[14][2]);   // L1 CRX(9,10)
        vst<0,1,2,11>(R, I, re, im, pb);
    }
    __syncthreads();

    // ---- Pass 5: S={2,3,4,5}; L1 1q wires 8,7,6; CRX slots 15,16,17 ----
    {
        const int pb = swzc(mkbase<0,1,7,8,9, 6,10,11>(tid));
        vld<2,3,4,5>(R, I, re, im, pb);
        v1q<1>(R, I, GS[20]);
        v1q<2>(R, I, GS[19]);
        v1q<3>(R, I, GS[18]);
        vcrx0t<1>(R, I, CC[15][0], CC[15][1], CC[15][2]);   // CRX(8,9)
        vcrx<2,1>(R, I, CC[16][0], CC[16][1], CC[16][2]);   // CRX(7,8)
        vcrx<3,2>(R, I, CC[17][0], CC[17][1], CC[17][2]);   // CRX(6,7)
        vst<2,3,4,5>(R, I, re, im, pb);
    }
    __syncthreads();

    // ---- Pass 6: S={5,6,7,8}; L1 1q wires 5,4,3; CRX slots 18,19,20 ----
    {
        const int pb = swzc(mkbase<0,1,2,3,4, 9,10,11>(tid));
        vld<5,6,7,8>(R, I, re, im, pb);
        v1q<1>(R, I, GS[17]);
        v1q<2>(R, I, GS[16]);
        v1q<3>(R, I, GS[15]);
        vcrx0t<1>(R, I, CC[18][0], CC[18][1], CC[18][2]);   // CRX(5,6)
        vcrx<2,1>(R, I, CC[19][0], CC[19][1], CC[19][2]);   // CRX(4,5)
        vcrx<3,2>(R, I, CC[20][0], CC[20][1], CC[20][2]);   // CRX(3,4)
        vst<5,6,7,8>(R, I, re, im, pb);
    }
    __syncthreads();

    // ---- Pass 7: S={8,9,10,11}; L1 1q wires 2,1; CRX slots 21,22,23; + expvals ----
    {
        const int pb = swzc(tid);
        vld<8,9,10,11>(R, I, re, im, pb);
        v1q<1>(R, I, GS[14]);                               // bit9 = wire2
        v1q<2>(R, I, GS[13]);                               // bit10 = wire1
        vcrx0t<1>(R, I, CC[21][0], CC[21][1], CC[21][2]);   // CRX(2,3)
        vcrx<2,1>(R, I, CC[22][0], CC[22][1], CC[22][2]);   // CRX(1,2)
        vcrx<3,2>(R, I, CC[23][0], CC[23][1], CC[23][2]);   // CRX(0,1)
        vst<8,9,10,11>(R, I, re, im, pb);

        // Z for all qubits, X/Y for qubits 0-3
        u64 tot2 = 0ull, d1v = 0ull, d2v = 0ull, d3v = 0ull;
#pragma unroll
        for (int m = 0; m < 8; m++) {
            const u64 p2 = f2fma(R[m], R[m], f2mul(I[m], I[m]));
            tot2 = f2add(tot2, p2);
            if (m & 1) d1v = f2add(d1v, p2);
            if (m & 2) d2v = f2add(d2v, p2);
            if (m & 4) d3v = f2add(d3v, p2);
        }
        float tlo, thi; upk(tot2, tlo, thi);
        const float tot = tlo + thi;
        const float d0 = thi;
        float a, b;
        upk(d1v, a, b); const float d1 = a + b;
        upk(d2v, a, b); const float d2 = a + b;
        upk(d3v, a, b); const float d3 = a + b;
        red_add(tot - 2.f*d0, &feats[24 + 3]);   // bit8  -> qubit3
        red_add(tot - 2.f*d1, &feats[24 + 2]);
        red_add(tot - 2.f*d2, &feats[24 + 1]);
        red_add(tot - 2.f*d3, &feats[24 + 0]);
#pragma unroll
        for (int fb = 0; fb < 8; fb++) {
            const float zv = ((tid >> fb) & 1) ? -tot : tot;
            red_add(zv, &feats[24 + (11 - fb)]); // free bit fb -> qubit 11-fb
        }
        vcross0(R, I, feats, 3);
        vcross<1>(R, I, feats, 2);
        vcross<2>(R, I, feats, 1);
        vcross<3>(R, I, feats, 0);
    }
    __syncthreads();

    // ---- Pass 8: X/Y for qubits 7,6,5,4 (bits 4,5,6,7) ----
    {
        const int pb = swzc(mkbase<0,1,2,3,9, 8,10,11>(tid));
        vld<4,5,6,7>(R, I, re, im, pb);
        vcross0(R, I, feats, 7);
        vcross<1>(R, I, feats, 6);
        vcross<2>(R, I, feats, 5);
        vcross<3>(R, I, feats, 4);
    }

    // ---- Pass 9: X/Y for qubits 11,10,9,8 (bits 0,1,2,3) ----
    {
        const int pb = swzc(mkbase<4,5,6,7,8, 9,10,11>(tid));
        vld<0,1,2,3>(R, I, re, im, pb);
        vcross0(R, I, feats, 11);
        vcross<1>(R, I, feats, 10);
        vcross<2>(R, I, feats, 9);
        vcross<3>(R, I, feats, 8);
    }
    __syncthreads();

    // ---- Linear head ----
    if (tid < NCLASSES) {
        float acc = bv[tid];
#pragma unroll
        for (int j = 0; j < NFEAT; ++j)
            acc += Wm[tid * NFEAT + j] * feats[j];
        out[(size_t)bidx * NCLASSES + tid] = acc;
    }
}

extern "C" void kernel_launch(void* const* d_in, const int* in_sizes, int n_in,
                              void* d_out, int out_size)
{
    const float* sv     = (const float*)d_in[0];  // [2048, 4096]
    const float* angles = (const float*)d_in[1];  // [96]
    const float* Wm     = (const float*)d_in[2];  // [10, 36]
    const float* bv     = (const float*)d_in[3];  // [10]
    float* out          = (float*)d_out;          // [2048, 10]
    (void)in_sizes; (void)n_in; (void)out_size;

    qsim_kernel<<<2048, THREADS>>>(sv, angles, Wm, bv, out);
}

// round 4
// speedup vs baseline: 1.4487x; 1.4487x over previous
#include <cuda_runtime.h>

#define NQ       12
#define DIM      4096
#define THREADS  256
#define NCLASSES 10
#define NFEAT    36

typedef unsigned long long u64;

struct Cx { float x, y; };
__device__ __forceinline__ Cx cmul(Cx a, Cx b) {
    return Cx{a.x * b.x - a.y * b.y, a.x * b.y + a.y * b.x};
}

// ---- f32x2 packed helpers (FFMA2 path, sm_103a) ----
__device__ __forceinline__ u64 pk(float lo, float hi) {
    u64 r; asm("mov.b64 %0, {%1,%2};" : "=l"(r) : "f"(lo), "f"(hi)); return r;
}
__device__ __forceinline__ void upk(u64 v, float& lo, float& hi) {
    asm("mov.b64 {%0,%1}, %2;" : "=f"(lo), "=f"(hi) : "l"(v));
}
__device__ __forceinline__ u64 f2fma(u64 a, u64 b, u64 c) {
    u64 r; asm("fma.rn.f32x2 %0, %1, %2, %3;" : "=l"(r) : "l"(a), "l"(b), "l"(c)); return r;
}
__device__ __forceinline__ u64 f2mul(u64 a, u64 b) {
    u64 r; asm("mul.rn.f32x2 %0, %1, %2;" : "=l"(r) : "l"(a), "l"(b)); return r;
}
__device__ __forceinline__ u64 f2add(u64 a, u64 b) {
    u64 r; asm("add.rn.f32x2 %0, %1, %2;" : "=l"(r) : "l"(a), "l"(b)); return r;
}
__device__ __forceinline__ u64 splat(float x) { return pk(x, x); }
__device__ __forceinline__ u64 swap2(u64 v) { float lo, hi; upk(v, lo, hi); return pk(hi, lo); }

// ---- addressing ----
__device__ __forceinline__ int swzc(int i) { return i ^ ((i >> 5) & 31); }

template<int S0,int S1,int S2,int S3>
__device__ __forceinline__ int offj(int j) {
    return ((j & 1) << S0) | (((j >> 1) & 1) << S1) | (((j >> 2) & 1) << S2) | (((j >> 3) & 1) << S3);
}
template<int L0,int L1,int L2,int L3,int L4,int W0,int W1,int W2>
__device__ __forceinline__ int mkbase(int t) {
    return ((t & 1) << L0) | (((t >> 1) & 1) << L1) | (((t >> 2) & 1) << L2) |
           (((t >> 3) & 1) << L3) | (((t >> 4) & 1) << L4) |
           (((t >> 5) & 1) << W0) | (((t >> 6) & 1) << W1) | (((t >> 7) & 1) << W2);
}

template<int S0,int S1,int S2,int S3>
__device__ __forceinline__ void vld(u64 R[8], u64 I[8], const float* re, const float* im, int pb) {
#pragma unroll
    for (int m = 0; m < 8; m++) {
        const int ad0 = pb ^ swzc(offj<S0,S1,S2,S3>(2*m));
        const int ad1 = pb ^ swzc(offj<S0,S1,S2,S3>(2*m + 1));
        R[m] = pk(re[ad0], re[ad1]);
        I[m] = pk(im[ad0], im[ad1]);
    }
}
template<int S0,int S1,int S2,int S3>
__device__ __forceinline__ void vst(const u64 R[8], const u64 I[8], float* re, float* im, int pb) {
#pragma unroll
    for (int m = 0; m < 8; m++) {
        const int ad0 = pb ^ swzc(offj<S0,S1,S2,S3>(2*m));
        const int ad1 = pb ^ swzc(offj<S0,S1,S2,S3>(2*m + 1));
        float lo, hi;
        upk(R[m], lo, hi); re[ad0] = lo; re[ad1] = hi;
        upk(I[m], lo, hi); im[ad0] = lo; im[ad1] = hi;
    }
}

// ---- gate kernels ----
// GS: [0]u00x [1]u01x [2]u10x [3]u11x [4]u00y [5]u01y [6]u10y [7]u11y [8..11] negated y's
template<int K>
__device__ __forceinline__ void v1q(u64 R[8], u64 I[8], const u64* g) {
#pragma unroll
    for (int m = 0; m < 8; m++) {
        if (!((m >> (K-1)) & 1)) {
            const int m1 = m | (1 << (K-1));
            const u64 a = R[m], ai = I[m], b = R[m1], bi = I[m1];
            R[m]  = f2fma(g[0], a, f2fma(g[8],  ai, f2fma(g[1], b, f2mul(g[9],  bi))));
            I[m]  = f2fma(g[4], a, f2fma(g[0],  ai, f2fma(g[5], b, f2mul(g[1],  bi))));
            R[m1] = f2fma(g[2], a, f2fma(g[10], ai, f2fma(g[3], b, f2mul(g[11], bi))));
            I[m1] = f2fma(g[6], a, f2fma(g[2],  ai, f2fma(g[7], b, f2mul(g[3],  bi))));
        }
    }
}

// GP: [0]A={u00x,u10x} [1]B={u01x,u11x} [2]C={u00y,u10y} [3]D={u01y,u11y} [4]-C [5]-D
__device__ __forceinline__ void v2q(u64 R[8], u64 I[8], const u64* p) {
#pragma unroll
    for (int m = 0; m < 8; m++) {
        float ar0, ar1, ai0, ai1;
        upk(R[m], ar0, ar1); upk(I[m], ai0, ai1);
        const u64 sr0 = splat(ar0), sr1 = splat(ar1), si0 = splat(ai0), si1 = splat(ai1);
        R[m] = f2fma(p[0], sr0, f2fma(p[4], si0, f2fma(p[1], sr1, f2mul(p[5], si1))));
        I[m] = f2fma(p[2], sr0, f2fma(p[0], si0, f2fma(p[3], sr1, f2mul(p[1], si1))));
    }
}
__device__ __forceinline__ void v2q_real(u64 R[8], u64 I[8], const u64* p) {
#pragma unroll
    for (int m = 0; m < 8; m++) {
        float ar0, ar1;
        upk(R[m], ar0, ar1);
        const u64 sr0 = splat(ar0), sr1 = splat(ar1);
        R[m] = f2fma(p[0], sr0, f2mul(p[1], sr1));
        I[m] = f2fma(p[2], sr0, f2mul(p[3], sr1));
    }
}

template<int KC,int KT>
__device__ __forceinline__ void vcrx(u64 R[8], u64 I[8], const u64* q) {
#pragma unroll
    for (int m = 0; m < 8; m++) {
        if (((m >> (KC-1)) & 1) && !((m >> (KT-1)) & 1)) {
            const int m1 = m | (1 << (KT-1));
            const u64 a = R[m], ai = I[m], b = R[m1], bi = I[m1];
            R[m]  = f2fma(q[0], a,  f2mul(q[1], bi));
            I[m]  = f2fma(q[0], ai, f2mul(q[2], b));
            R[m1] = f2fma(q[0], b,  f2mul(q[1], ai));
            I[m1] = f2fma(q[0], bi, f2mul(q[2], a));
        }
    }
}
template<int KC>
__device__ __forceinline__ void vcrx0t(u64 R[8], u64 I[8], const u64* q) {
#pragma unroll
    for (int m = 0; m < 8; m++) {
        if ((m >> (KC-1)) & 1) {
            const u64 swI = swap2(I[m]), swR = swap2(R[m]);
            R[m] = f2fma(q[0], R[m], f2mul(q[1], swI));
            I[m] = f2fma(q[0], I[m], f2mul(q[2], swR));
        }
    }
}
// ctrl = lane bit: q[0]={1,c} q[1]={0,s} q[2]={0,-s}
template<int KT>
__device__ __forceinline__ void vcrx0c(u64 R[8], u64 I[8], const u64* q) {
#pragma unroll
    for (int m = 0; m < 8; m++) {
        if (!((m >> (KT-1)) & 1)) {
            const int m1 = m | (1 << (KT-1));
            const u64 Ra = R[m], Ia = I[m], Rb = R[m1], Ib = I[m1];
            R[m]  = f2fma(q[0], Ra, f2mul(q[1], Ib));
            I[m]  = f2fma(q[0], Ia, f2mul(q[2], Rb));
            R[m1] = f2fma(q[0], Rb, f2mul(q[1], Ia));
            I[m1] = f2fma(q[0], Ib, f2mul(q[2], Ra));
        }
    }
}

__device__ __forceinline__ void red_add(float v, float* dst) {
#pragma unroll
    for (int o = 16; o > 0; o >>= 1) v += __shfl_xor_sync(0xffffffffu, v, o);
    if ((threadIdx.x & 31) == 0) atomicAdd(dst, v);
}

template<int K>
__device__ __forceinline__ void vcross(const u64 R[8], const u64 I[8], float* feats, int q) {
    u64 cr2 = 0ull, cip = 0ull, cin = 0ull;
#pragma unroll
    for (int m = 0; m < 8; m++) {
        if (!((m >> (K-1)) & 1)) {
            const int m1 = m | (1 << (K-1));
            cr2 = f2fma(R[m], R[m1], f2fma(I[m], I[m1], cr2));
            cip = f2fma(R[m], I[m1], cip);
            cin = f2fma(I[m], R[m1], cin);
        }
    }
    float a, b;  upk(cr2, a, b); const float cr = a + b;
    float p0, p1, n0, n1; upk(cip, p0, p1); upk(cin, n0, n1);
    const float ci = (p0 - n0) + (p1 - n1);
    red_add(2.f * cr, &feats[q]);
    red_add(2.f * ci, &feats[NQ + q]);
}
__device__ __forceinline__ void vcross0(const u64 R[8], const u64 I[8], float* feats, int q) {
    float cr = 0.f, ci = 0.f;
#pragma unroll
    for (int m = 0; m < 8; m++) {
        float r0, r1, i0, i1;
        upk(R[m], r0, r1); upk(I[m], i0, i1);
        cr = fmaf(r0, r1, fmaf(i0, i1, cr));
        ci = fmaf(r0, i1, ci) - i0 * r1;
    }
    red_add(2.f * cr, &feats[q]);
    red_add(2.f * ci, &feats[NQ + q]);
}

__global__ __launch_bounds__(THREADS, 2)
void qsim_kernel(const float* __restrict__ sv,
                 const float* __restrict__ angles,
                 const float* __restrict__ Wm,
                 const float* __restrict__ bv,
                 float* __restrict__ out)
{
    __shared__ float re[DIM];
    __shared__ float im[DIM];
    __shared__ u64 GS[24][12];
    __shared__ u64 GP[24][6];
    __shared__ u64 CC[24][3];
    __shared__ u64 CL[24][3];
    __shared__ float feats[NFEAT];

    const int tid  = threadIdx.x;
    const int bidx = blockIdx.x;

    if (tid < 24) {
        const int layer = tid / NQ;
        const int wire  = tid % NQ;
        const int base  = layer * 48;
        const float tx = angles[base + wire];
        const float ty = angles[base + 12 + wire];
        const float tz = angles[base + 24 + wire];
        const float cxv = cosf(0.5f*tx), sxv = sinf(0.5f*tx);
        const float cyv = cosf(0.5f*ty), syv = sinf(0.5f*ty);
        const float czv = cosf(0.5f*tz), szv = sinf(0.5f*tz);
        Cx m00{cyv*cxv,  syv*sxv};
        Cx m01{-syv*cxv, -cyv*sxv};
        Cx m10{syv*cxv,  -cyv*sxv};
        Cx m11{cyv*cxv,  -syv*sxv};
        Cx ezm{czv, -szv}, ezp{czv, szv};
        Cx u00 = cmul(ezm, m00), u01 = cmul(ezm, m01);
        Cx u10 = cmul(ezp, m10), u11 = cmul(ezp, m11);
        GS[tid][0]  = splat(u00.x); GS[tid][1]  = splat(u01.x);
        GS[tid][2]  = splat(u10.x); GS[tid][3]  = splat(u11.x);
        GS[tid][4]  = splat(u00.y); GS[tid][5]  = splat(u01.y);
        GS[tid][6]  = splat(u10.y); GS[tid][7]  = splat(u11.y);
        GS[tid][8]  = splat(-u00.y); GS[tid][9]  = splat(-u01.y);
        GS[tid][10] = splat(-u10.y); GS[tid][11] = splat(-u11.y);
        GP[tid][0] = pk(u00.x, u10.x); GP[tid][1] = pk(u01.x, u11.x);
        GP[tid][2] = pk(u00.y, u10.y); GP[tid][3] = pk(u01.y, u11.y);
        GP[tid][4] = pk(-u00.y, -u10.y); GP[tid][5] = pk(-u01.y, -u11.y);
        const float tc = angles[base + 36 + wire];
        const float c = cosf(0.5f*tc), s = sinf(0.5f*tc);
        CC[tid][0] = pk(c, c); CC[tid][1] = pk(s, s); CC[tid][2] = pk(-s, -s);
        CL[tid][0] = pk(1.f, c); CL[tid][1] = pk(0.f, s); CL[tid][2] = pk(0.f, -s);
    }
    if (tid < NFEAT) feats[tid] = 0.0f;
    __syncthreads();

    u64 R[8], I[8];

    // ---- Pass 1: S={8,9,10,11}; L0 1q wires 0-3; CRX slots 0,1,2 ----
    {
        const float* in = sv + (size_t)bidx * DIM;
#pragma unroll
        for (int m = 0; m < 8; m++) {
            R[m] = pk(in[((2*m) << 8) | tid], in[((2*m+1) << 8) | tid]);
            I[m] = 0ull;
        }
        v2q_real(R, I, GP[3]);
        v1q<1>(R, I, GS[2]);
        v1q<2>(R, I, GS[1]);
        v1q<3>(R, I, GS[0]);
        vcrx<3,2>(R, I, CC[0]);
        vcrx<2,1>(R, I, CC[1]);
        vcrx0t<1>(R, I, CC[2]);
        vst<8,9,10,11>(R, I, re, im, swzc(tid));
    }
    __syncthreads();

    // ---- Pass 2: S={5,6,7,8}; L0 1q wires 6,5,4; CRX slots 3,4,5 ----
    {
        const int pb = swzc(mkbase<0,1,2,3,4, 9,10,11>(tid));
        vld<5,6,7,8>(R, I, re, im, pb);
        v2q(R, I, GP[6]);
        v1q<1>(R, I, GS[5]);
        v1q<2>(R, I, GS[4]);
        vcrx<3,2>(R, I, CC[3]);
        vcrx<2,1>(R, I, CC[4]);
        vcrx0t<1>(R, I, CC[5]);
        vst<5,6,7,8>(R, I, re, im, pb);
    }
    __syncthreads();

    // ---- Pass 3: S={2,3,4,5}; L0 1q wires 9,8,7; CRX slots 6,7,8 ----
    {
        const int pb = swzc(mkbase<0,1,7,8,9, 6,10,11>(tid));
        vld<2,3,4,5>(R, I, re, im, pb);
        v2q(R, I, GP[9]);
        v1q<1>(R, I, GS[8]);
        v1q<2>(R, I, GS[7]);
        vcrx<3,2>(R, I, CC[6]);
        vcrx<2,1>(R, I, CC[7]);
        vcrx0t<1>(R, I, CC[8]);
        vst<2,3,4,5>(R, I, re, im, pb);
    }
    __syncthreads();

    // ---- Pass 4 (mega): S={0,1,2,11} ----
    {
        const int pb = swzc(mkbase<3,4,5,6,7, 8,9,10>(tid));
        vld<0,1,2,11>(R, I, re, im, pb);
        v2q(R, I, GP[11]);
        v1q<1>(R, I, GS[10]);
        vcrx<2,1>(R, I, CC[9]);
        vcrx0t<1>(R, I, CC[10]);
        vcrx0c<3>(R, I, CL[11]);
        v2q(R, I, GP[23]);
        v1q<1>(R, I, GS[22]);
        v1q<2>(R, I, GS[21]);
        v1q<3>(R, I, GS[12]);
        vcrx0c<3>(R, I, CL[12]);
        vcrx0t<1>(R, I, CC[13]);
        vcrx<2,1>(R, I, CC[14]);
        vst<0,1,2,11>(R, I, re, im, pb);
    }
    __syncthreads();

    // ---- Pass 5: S={2,3,4,5}; L1 1q wires 8,7,6; CRX slots 15,16,17 ----
    {
        const int pb = swzc(mkbase<0,1,7,8,9, 6,10,11>(tid));
        vld<2,3,4,5>(R, I, re, im, pb);
        v1q<1>(R, I, GS[20]);
        v1q<2>(R, I, GS[19]);
        v1q<3>(R, I, GS[18]);
        vcrx0t<1>(R, I, CC[15]);
        vcrx<2,1>(R, I, CC[16]);
        vcrx<3,2>(R, I, CC[17]);
        vst<2,3,4,5>(R, I, re, im, pb);
    }
    __syncthreads();

    // ---- Pass 6: S={5,6,7,8}; L1 1q wires 5,4,3; CRX slots 18,19,20 ----
    {
        const int pb = swzc(mkbase<0,1,2,3,4, 9,10,11>(tid));
        vld<5,6,7,8>(R, I, re, im, pb);
        v1q<1>(R, I, GS[17]);
        v1q<2>(R, I, GS[16]);
        v1q<3>(R, I, GS[15]);
        vcrx0t<1>(R, I, CC[18]);
        vcrx<2,1>(R, I, CC[19]);
        vcrx<3,2>(R, I, CC[20]);
        vst<5,6,7,8>(R, I, re, im, pb);
    }
    __syncthreads();

    // ---- Pass 7: S={8,9,10,11}; L1 1q wires 2,1; CRX slots 21,22,23; + expvals ----
    {
        const int pb = swzc(tid);
        vld<8,9,10,11>(R, I, re, im, pb);
        v1q<1>(R, I, GS[14]);
        v1q<2>(R, I, GS[13]);
        vcrx0t<1>(R, I, CC[21]);
        vcrx<2,1>(R, I, CC[22]);
        vcrx<3,2>(R, I, CC[23]);
        vst<8,9,10,11>(R, I, re, im, pb);

        u64 tot2 = 0ull, d1v = 0ull, d2v = 0ull, d3v = 0ull;
#pragma unroll
        for (int m = 0; m < 8; m++) {
            const u64 p2 = f2fma(R[m], R[m], f2mul(I[m], I[m]));
            tot2 = f2add(tot2, p2);
            if (m & 1) d1v = f2add(d1v, p2);
            if (m & 2) d2v = f2add(d2v, p2);
            if (m & 4) d3v = f2add(d3v, p2);
        }
        float tlo, thi; upk(tot2, tlo, thi);
        const float tot = tlo + thi;
        const float d0 = thi;
        float a, b;
        upk(d1v, a, b); const float d1 = a + b;
        upk(d2v, a, b); const float d2 = a + b;
        upk(d3v, a, b); const float d3 = a + b;
        red_add(tot - 2.f*d0, &feats[24 + 3]);
        red_add(tot - 2.f*d1, &feats[24 + 2]);
        red_add(tot - 2.f*d2, &feats[24 + 1]);
        red_add(tot - 2.f*d3, &feats[24 + 0]);
#pragma unroll
        for (int fb = 0; fb < 8; fb++) {
            const float zv = ((tid >> fb) & 1) ? -tot : tot;
            red_add(zv, &feats[24 + (11 - fb)]);
        }
        vcross0(R, I, feats, 3);
        vcross<1>(R, I, feats, 2);
        vcross<2>(R, I, feats, 1);
        vcross<3>(R, I, feats, 0);
    }
    __syncthreads();

    // ---- Pass 8: X/Y qubits 7,6,5,4 ----
    {
        const int pb = swzc(mkbase<0,1,2,3,9, 8,10,11>(tid));
        vld<4,5,6,7>(R, I, re, im, pb);
        vcross0(R, I, feats, 7);
        vcross<1>(R, I, feats, 6);
        vcross<2>(R, I, feats, 5);
        vcross<3>(R, I, feats, 4);
    }

    // ---- Pass 9: X/Y qubits 11,10,9,8 ----
    {
        const int pb = swzc(mkbase<4,5,6,7,8, 9,10,11>(tid));
        vld<0,1,2,3>(R, I, re, im, pb);
        vcross0(R, I, feats, 11);
        vcross<1>(R, I, feats, 10);
        vcross<2>(R, I, feats, 9);
        vcross<3>(R, I, feats, 8);
    }
    __syncthreads();

    // ---- Linear head ----
    if (tid < NCLASSES) {
        float acc = bv[tid];
#pragma unroll
        for (int j = 0; j < NFEAT; ++j)
            acc += Wm[tid * NFEAT + j] * feats[j];
        out[(size_t)bidx * NCLASSES + tid] = acc;
    }
}

extern "C" void kernel_launch(void* const* d_in, const int* in_sizes, int n_in,
                              void* d_out, int out_size)
{
    const float* sv     = (const float*)d_in[0];
    const float* angles = (const float*)d_in[1];
    const float* Wm     = (const float*)d_in[2];
    const float* bv     = (const float*)d_in[3];
    float* out          = (float*)d_out;
    (void)in_sizes; (void)n_in; (void)out_size;

    qsim_kernel<<<2048, THREADS>>>(sv, angles, Wm, bv, out);
}

// round 5
// speedup vs baseline: 1.5297x; 1.0559x over previous
#include <cuda_runtime.h>

#define NQ       12
#define DIM      4096
#define THREADS  256
#define NCLASSES 10
#define NFEAT    36

typedef unsigned long long u64;

struct Cx { float x, y; };
__device__ __forceinline__ Cx cmul(Cx a, Cx b) {
    return Cx{a.x * b.x - a.y * b.y, a.x * b.y + a.y * b.x};
}

// ---- f32x2 helpers ----
__device__ __forceinline__ u64 pk(float lo, float hi) {
    u64 r; asm("mov.b64 %0, {%1,%2};" : "=l"(r) : "f"(lo), "f"(hi)); return r;
}
__device__ __forceinline__ void upk(u64 v, float& lo, float& hi) {
    asm("mov.b64 {%0,%1}, %2;" : "=f"(lo), "=f"(hi) : "l"(v));
}
__device__ __forceinline__ u64 f2fma(u64 a, u64 b, u64 c) {
    u64 r; asm("fma.rn.f32x2 %0, %1, %2, %3;" : "=l"(r) : "l"(a), "l"(b), "l"(c)); return r;
}
__device__ __forceinline__ u64 f2mul(u64 a, u64 b) {
    u64 r; asm("mul.rn.f32x2 %0, %1, %2;" : "=l"(r) : "l"(a), "l"(b)); return r;
}
__device__ __forceinline__ u64 f2add(u64 a, u64 b) {
    u64 r; asm("add.rn.f32x2 %0, %1, %2;" : "=l"(r) : "l"(a), "l"(b)); return r;
}
__device__ __forceinline__ u64 splat(float x) { return pk(x, x); }

// ---- addressing ----
__device__ __forceinline__ int swzc(int i) { return i ^ ((i >> 5) & 31); }

template<int S0,int S1,int S2,int S3>
__device__ __forceinline__ int offj(int j) {
    return ((j & 1) << S0) | (((j >> 1) & 1) << S1) | (((j >> 2) & 1) << S2) | (((j >> 3) & 1) << S3);
}
template<int L0,int L1,int L2,int L3,int L4,int W0,int W1,int W2>
__device__ __forceinline__ int mkbase(int t) {
    return ((t & 1) << L0) | (((t >> 1) & 1) << L1) | (((t >> 2) & 1) << L2) |
           (((t >> 3) & 1) << L3) | (((t >> 4) & 1) << L4) |
           (((t >> 5) & 1) << W0) | (((t >> 6) & 1) << W1) | (((t >> 7) & 1) << W2);
}

// Each u64 in re2/im2 packs {batch0, batch1} of one amplitude.
template<int S0,int S1,int S2,int S3>
__device__ __forceinline__ void vld(u64 R[16], u64 I[16], const u64* re2, const u64* im2, int pb) {
#pragma unroll
    for (int j = 0; j < 16; j++) {
        const int ad = pb ^ swzc(offj<S0,S1,S2,S3>(j));
        R[j] = re2[ad]; I[j] = im2[ad];
    }
}
template<int S0,int S1,int S2,int S3>
__device__ __forceinline__ void vst(const u64 R[16], const u64 I[16], u64* re2, u64* im2, int pb) {
#pragma unroll
    for (int j = 0; j < 16; j++) {
        const int ad = pb ^ swzc(offj<S0,S1,S2,S3>(j));
        re2[ad] = R[j]; im2[ad] = I[j];
    }
}

// ---- gates (uniform over both lanes = both batches) ----
// GS: [0]u00x [1]u01x [2]u10x [3]u11x [4]u00y [5]u01y [6]u10y [7]u11y [8..11] = -y's
template<int K>
__device__ __forceinline__ void v1q(u64 R[16], u64 I[16], const u64* g) {
#pragma unroll
    for (int j = 0; j < 16; j++) {
        if (!((j >> K) & 1)) {
            const int j1 = j | (1 << K);
            const u64 a = R[j], ai = I[j], b = R[j1], bi = I[j1];
            R[j]  = f2fma(g[0], a, f2fma(g[8],  ai, f2fma(g[1], b, f2mul(g[9],  bi))));
            I[j]  = f2fma(g[4], a, f2fma(g[0],  ai, f2fma(g[5], b, f2mul(g[1],  bi))));
            R[j1] = f2fma(g[2], a, f2fma(g[10], ai, f2fma(g[3], b, f2mul(g[11], bi))));
            I[j1] = f2fma(g[6], a, f2fma(g[2],  ai, f2fma(g[7], b, f2mul(g[3],  bi))));
        }
    }
}
// first gate on a purely real state (I == 0)
template<int K>
__device__ __forceinline__ void v1q_real(u64 R[16], u64 I[16], const u64* g) {
#pragma unroll
    for (int j = 0; j < 16; j++) {
        if (!((j >> K) & 1)) {
            const int j1 = j | (1 << K);
            const u64 a = R[j], b = R[j1];
            R[j]  = f2fma(g[0], a, f2mul(g[1], b));
            I[j]  = f2fma(g[4], a, f2mul(g[5], b));
            R[j1] = f2fma(g[2], a, f2mul(g[3], b));
            I[j1] = f2fma(g[6], a, f2mul(g[7], b));
        }
    }
}
// CRX on local bits: q[0]={c,c} q[1]={s,s} q[2]={-s,-s}
template<int KC,int KT>
__device__ __forceinline__ void vcrx(u64 R[16], u64 I[16], const u64* q) {
#pragma unroll
    for (int j = 0; j < 16; j++) {
        if (((j >> KC) & 1) && !((j >> KT) & 1)) {
            const int j1 = j | (1 << KT);
            const u64 a = R[j], ai = I[j], b = R[j1], bi = I[j1];
            R[j]  = f2fma(q[0], a,  f2mul(q[1], bi));
            I[j]  = f2fma(q[0], ai, f2mul(q[2], b));
            R[j1] = f2fma(q[0], b,  f2mul(q[1], ai));
            I[j1] = f2fma(q[0], bi, f2mul(q[2], a));
        }
    }
}

__device__ __forceinline__ void red_add(float v, float* dst) {
#pragma unroll
    for (int o = 16; o > 0; o >>= 1) v += __shfl_xor_sync(0xffffffffu, v, o);
    if ((threadIdx.x & 31) == 0) atomicAdd(dst, v);
}
// packed reduce: lane lo -> feats0[q], lane hi -> feats1[q]
__device__ __forceinline__ void red_add2(u64 v, float* f0, float* f1) {
    float a, b; upk(v, a, b);
    red_add(a, f0);
    red_add(b, f1);
}

// <X>,<Y> across local bit K (both batches at once)
template<int K>
__device__ __forceinline__ void vcross(const u64 R[16], const u64 I[16],
                                       float* feats0, float* feats1, int q) {
    u64 cr2 = 0ull, cip = 0ull, cin = 0ull;
#pragma unroll
    for (int j = 0; j < 16; j++) {
        if (!((j >> K) & 1)) {
            const int j1 = j | (1 << K);
            cr2 = f2fma(R[j], R[j1], f2fma(I[j], I[j1], cr2));
            cip = f2fma(R[j], I[j1], cip);
            cin = f2fma(I[j], R[j1], cin);
        }
    }
    float c0, c1, p0, p1, n0, n1;
    upk(cr2, c0, c1); upk(cip, p0, p1); upk(cin, n0, n1);
    red_add(2.f * c0, &feats0[q]);
    red_add(2.f * c1, &feats1[q]);
    red_add(2.f * (p0 - n0), &feats0[NQ + q]);
    red_add(2.f * (p1 - n1), &feats1[NQ + q]);
}

__global__ __launch_bounds__(THREADS, 2)
void qsim_kernel(const float* __restrict__ sv,
                 const float* __restrict__ angles,
                 const float* __restrict__ Wm,
                 const float* __restrict__ bv,
                 float* __restrict__ out)
{
    extern __shared__ u64 smem_state[];     // re2[4096] ++ im2[4096]  (64 KB)
    u64* re2 = smem_state;
    u64* im2 = smem_state + DIM;

    __shared__ u64 GS[24][12];
    __shared__ u64 CC[24][3];
    __shared__ float feats[2][NFEAT];

    const int tid  = threadIdx.x;
    const int bidx = blockIdx.x;

    if (tid < 24) {
        const int layer = tid / NQ;
        const int wire  = tid % NQ;
        const int base  = layer * 48;
        const float tx = angles[base + wire];
        const float ty = angles[base + 12 + wire];
        const float tz = angles[base + 24 + wire];
        const float cxv = cosf(0.5f*tx), sxv = sinf(0.5f*tx);
        const float cyv = cosf(0.5f*ty), syv = sinf(0.5f*ty);
        const float czv = cosf(0.5f*tz), szv = sinf(0.5f*tz);
        Cx m00{cyv*cxv,  syv*sxv};
        Cx m01{-syv*cxv, -cyv*sxv};
        Cx m10{syv*cxv,  -cyv*sxv};
        Cx m11{cyv*cxv,  -syv*sxv};
        Cx ezm{czv, -szv}, ezp{czv, szv};
        Cx u00 = cmul(ezm, m00), u01 = cmul(ezm, m01);
        Cx u10 = cmul(ezp, m10), u11 = cmul(ezp, m11);
        GS[tid][0]  = splat(u00.x); GS[tid][1]  = splat(u01.x);
        GS[tid][2]  = splat(u10.x); GS[tid][3]  = splat(u11.x);
        GS[tid][4]  = splat(u00.y); GS[tid][5]  = splat(u01.y);
        GS[tid][6]  = splat(u10.y); GS[tid][7]  = splat(u11.y);
        GS[tid][8]  = splat(-u00.y); GS[tid][9]  = splat(-u01.y);
        GS[tid][10] = splat(-u10.y); GS[tid][11] = splat(-u11.y);
        const float tc = angles[base + 36 + wire];
        const float c = cosf(0.5f*tc), s = sinf(0.5f*tc);
        CC[tid][0] = pk(c, c); CC[tid][1] = pk(s, s); CC[tid][2] = pk(-s, -s);
    }
    if (tid < 2 * NFEAT) feats[0][tid] = 0.0f;   // feats is contiguous [2][36]
    __syncthreads();

    u64 R[16], I[16];

    // ---- Pass 1: S={8,9,10,11} (wires 3,2,1,0); load gmem; L0 1q; CRX 0,1,2 ----
    {
        const float* in0 = sv + ((size_t)(2 * bidx))     * DIM;
        const float* in1 = sv + ((size_t)(2 * bidx) + 1) * DIM;
#pragma unroll
        for (int j = 0; j < 16; j++) {
            const int idx = (j << 8) | tid;
            R[j] = pk(in0[idx], in1[idx]);
            I[j] = 0ull;
        }
        v1q_real<0>(R, I, GS[3]);   // wire3, state real
        v1q<1>(R, I, GS[2]);
        v1q<2>(R, I, GS[1]);
        v1q<3>(R, I, GS[0]);
        vcrx<3,2>(R, I, CC[0]);     // CRX(0,1)
        vcrx<2,1>(R, I, CC[1]);     // CRX(1,2)
        vcrx<1,0>(R, I, CC[2]);     // CRX(2,3)
        vst<8,9,10,11>(R, I, re2, im2, swzc(tid));
    }
    __syncthreads();

    // ---- Pass 2: S={5,6,7,8} (wires 6,5,4,3); L0 1q 6,5,4; CRX 3,4,5 ----
    {
        const int pb = swzc(mkbase<0,1,2,3,4, 9,10,11>(tid));
        vld<5,6,7,8>(R, I, re2, im2, pb);
        v1q<0>(R, I, GS[6]);
        v1q<1>(R, I, GS[5]);
        v1q<2>(R, I, GS[4]);
        vcrx<3,2>(R, I, CC[3]);
        vcrx<2,1>(R, I, CC[4]);
        vcrx<1,0>(R, I, CC[5]);
        vst<5,6,7,8>(R, I, re2, im2, pb);
    }
    __syncthreads();

    // ---- Pass 3: S={2,3,4,5} (wires 9,8,7,6); L0 1q 9,8,7; CRX 6,7,8 ----
    {
        const int pb = swzc(mkbase<0,1,7,8,9, 6,10,11>(tid));
        vld<2,3,4,5>(R, I, re2, im2, pb);
        v1q<0>(R, I, GS[9]);
        v1q<1>(R, I, GS[8]);
        v1q<2>(R, I, GS[7]);
        vcrx<3,2>(R, I, CC[6]);
        vcrx<2,1>(R, I, CC[7]);
        vcrx<1,0>(R, I, CC[8]);
        vst<2,3,4,5>(R, I, re2, im2, pb);
    }
    __syncthreads();

    // ---- Pass 4 (mega): S={0,1,2,11} (wires 11,10,9,0) ----
    {
        const int pb = swzc(mkbase<5,6,7,3,4, 8,9,10>(tid));
        vld<0,1,2,11>(R, I, re2, im2, pb);
        v1q<0>(R, I, GS[11]);       // L0 wire11
        v1q<1>(R, I, GS[10]);       // L0 wire10
        vcrx<2,1>(R, I, CC[9]);     // CRX(9,10)
        vcrx<1,0>(R, I, CC[10]);    // CRX(10,11)
        vcrx<0,3>(R, I, CC[11]);    // CRX(11,0)
        v1q<0>(R, I, GS[23]);       // L1 wire11
        v1q<1>(R, I, GS[22]);       // L1 wire10
        v1q<2>(R, I, GS[21]);       // L1 wire9
        v1q<3>(R, I, GS[12]);       // L1 wire0
        vcrx<0,3>(R, I, CC[12]);    // L1 CRX(11,0)
        vcrx<1,0>(R, I, CC[13]);    // L1 CRX(10,11)
        vcrx<2,1>(R, I, CC[14]);    // L1 CRX(9,10)
        vst<0,1,2,11>(R, I, re2, im2, pb);
    }
    __syncthreads();

    // ---- Pass 5: S={2,3,4,5}; L1 1q 8,7,6; CRX 15,16,17 ----
    {
        const int pb = swzc(mkbase<0,1,7,8,9, 6,10,11>(tid));
        vld<2,3,4,5>(R, I, re2, im2, pb);
        v1q<1>(R, I, GS[20]);
        v1q<2>(R, I, GS[19]);
        v1q<3>(R, I, GS[18]);
        vcrx<1,0>(R, I, CC[15]);    // CRX(8,9)
        vcrx<2,1>(R, I, CC[16]);    // CRX(7,8)
        vcrx<3,2>(R, I, CC[17]);    // CRX(6,7)
        vst<2,3,4,5>(R, I, re2, im2, pb);
    }
    __syncthreads();

    // ---- Pass 6: S={5,6,7,8}; L1 1q 5,4,3; CRX 18,19,20 ----
    {
        const int pb = swzc(mkbase<0,1,2,3,4, 9,10,11>(tid));
        vld<5,6,7,8>(R, I, re2, im2, pb);
        v1q<1>(R, I, GS[17]);
        v1q<2>(R, I, GS[16]);
        v1q<3>(R, I, GS[15]);
        vcrx<1,0>(R, I, CC[18]);    // CRX(5,6)
        vcrx<2,1>(R, I, CC[19]);    // CRX(4,5)
        vcrx<3,2>(R, I, CC[20]);    // CRX(3,4)
        vst<5,6,7,8>(R, I, re2, im2, pb);
    }
    __syncthreads();

    // ---- Pass 7: S={8,9,10,11}; L1 1q 2,1; CRX 21,22,23; + expvals ----
    {
        const int pb = swzc(tid);
        vld<8,9,10,11>(R, I, re2, im2, pb);
        v1q<1>(R, I, GS[14]);       // wire2
        v1q<2>(R, I, GS[13]);       // wire1
        vcrx<1,0>(R, I, CC[21]);    // CRX(2,3)
        vcrx<2,1>(R, I, CC[22]);    // CRX(1,2)
        vcrx<3,2>(R, I, CC[23]);    // CRX(0,1)
        vst<8,9,10,11>(R, I, re2, im2, pb);

        // Z for all qubits; X/Y for qubits 3,2,1,0 (local bits 0-3)
        u64 tot2 = 0ull, d0v = 0ull, d1v = 0ull, d2v = 0ull, d3v = 0ull;
#pragma unroll
        for (int j = 0; j < 16; j++) {
            const u64 p2 = f2fma(R[j], R[j], f2mul(I[j], I[j]));
            tot2 = f2add(tot2, p2);
            if (j & 1) d0v = f2add(d0v, p2);
            if (j & 2) d1v = f2add(d1v, p2);
            if (j & 4) d2v = f2add(d2v, p2);
            if (j & 8) d3v = f2add(d3v, p2);
        }
        float t0, t1, a0, a1;
        upk(tot2, t0, t1);
        upk(d0v, a0, a1); red_add(t0 - 2.f*a0, &feats[0][24+3]); red_add(t1 - 2.f*a1, &feats[1][24+3]);
        upk(d1v, a0, a1); red_add(t0 - 2.f*a0, &feats[0][24+2]); red_add(t1 - 2.f*a1, &feats[1][24+2]);
        upk(d2v, a0, a1); red_add(t0 - 2.f*a0, &feats[0][24+1]); red_add(t1 - 2.f*a1, &feats[1][24+1]);
        upk(d3v, a0, a1); red_add(t0 - 2.f*a0, &feats[0][24+0]); red_add(t1 - 2.f*a1, &feats[1][24+0]);
#pragma unroll
        for (int fb = 0; fb < 8; fb++) {
            const float s = ((tid >> fb) & 1) ? -1.f : 1.f;
            red_add(s * t0, &feats[0][24 + (11 - fb)]);
            red_add(s * t1, &feats[1][24 + (11 - fb)]);
        }
        vcross<0>(R, I, feats[0], feats[1], 3);
        vcross<1>(R, I, feats[0], feats[1], 2);
        vcross<2>(R, I, feats[0], feats[1], 1);
        vcross<3>(R, I, feats[0], feats[1], 0);
    }
    __syncthreads();

    // ---- Pass 8: S={4,5,6,7} (wires 7,6,5,4): X/Y ----
    {
        const int pb = swzc(mkbase<0,1,2,3,9, 8,10,11>(tid));
        vld<4,5,6,7>(R, I, re2, im2, pb);
        vcross<0>(R, I, feats[0], feats[1], 7);
        vcross<1>(R, I, feats[0], feats[1], 6);
        vcross<2>(R, I, feats[0], feats[1], 5);
        vcross<3>(R, I, feats[0], feats[1], 4);
    }

    // ---- Pass 9: S={0,1,2,3} (wires 11,10,9,8): X/Y ----
    {
        const int pb = swzc(mkbase<5,6,7,8,4, 9,10,11>(tid));
        vld<0,1,2,3>(R, I, re2, im2, pb);
        vcross<0>(R, I, feats[0], feats[1], 11);
        vcross<1>(R, I, feats[0], feats[1], 10);
        vcross<2>(R, I, feats[0], feats[1], 9);
        vcross<3>(R, I, feats[0], feats[1], 8);
    }
    __syncthreads();

    // ---- Linear head: 2 batches × 10 classes ----
    if (tid < 2 * NCLASSES) {
        const int batch = tid / NCLASSES;
        const int c     = tid % NCLASSES;
        float acc = bv[c];
#pragma unroll
        for (int j = 0; j < NFEAT; ++j)
            acc += Wm[c * NFEAT + j] * feats[batch][j];
        out[((size_t)(2 * bidx) + batch) * NCLASSES + c] = acc;
    }
}

extern "C" void kernel_launch(void* const* d_in, const int* in_sizes, int n_in,
                              void* d_out, int out_size)
{
    const float* sv     = (const float*)d_in[0];  // [2048, 4096]
    const float* angles = (const float*)d_in[1];  // [96]
    const float* Wm     = (const float*)d_in[2];  // [10, 36]
    const float* bv     = (const float*)d_in[3];  // [10]
    float* out          = (float*)d_out;          // [2048, 10]
    (void)in_sizes; (void)n_in; (void)out_size;

    const int smem_bytes = 2 * DIM * (int)sizeof(u64);  // 64 KB dynamic
    cudaFuncSetAttribute(qsim_kernel, cudaFuncAttributeMaxDynamicSharedMemorySize, smem_bytes);
    qsim_kernel<<<1024, THREADS, smem_bytes>>>(sv, angles, Wm, bv, out);
}